// round 11
// baseline (speedup 1.0000x reference)
#include <cuda_runtime.h>
#include <cuda_fp16.h>
#include <cstdint>

// Batched C[b,n,m] = sum_e A[b,n,e] * B[b,m,e]
// b=8, n=m=2048, e=1024, fp32 in/out.
// v10: cvt pre-kernel fp32->fp16 scratch; GEMM pure fp16: cp.async 4-stage
// ring, ldmatrix.x4, mma.sync m16n8k16. 128x256 CTA tile, 512 threads,
// 16 warps (4x4) of 32x64 tiles. Scheduling fixes: hoisted LDSM per k-step,
// per-warp k-step rotation (decorrelates same-SMSP warps), streaming C stores.

#define TM 128
#define TN 256
#define BKH 64
#define NSTG 4
#define EDIM 1024
#define NDIM 2048
#define MDIM 2048
#define NB 8
#define NCHUNK (EDIM / BKH)      // 16
#define A_BYTES (TM * BKH * 2)   // 16384
#define B_BYTES (TN * BKH * 2)   // 32768
#define STG (A_BYTES + B_BYTES)  // 49152
#define SMEM_BYTES (NSTG * STG)  // 196608

#define NELEM (NB * NDIM * EDIM)
__device__ uint4 g_Ah[NELEM / 8];
__device__ uint4 g_Bh[NELEM / 8];

__global__ void __launch_bounds__(256)
cvt_f32_f16(const float4* __restrict__ s0, uint4* __restrict__ d0,
            const float4* __restrict__ s1, uint4* __restrict__ d1, int n8) {
    const float4* src = blockIdx.y ? s1 : s0;
    uint4* dst = blockIdx.y ? d1 : d0;
    int i = blockIdx.x * blockDim.x + threadIdx.x;
    int stride = gridDim.x * blockDim.x;
    for (; i < n8; i += stride) {
        float4 v0 = src[2 * i];
        float4 v1 = src[2 * i + 1];
        uint4 o;
        asm("cvt.rn.f16x2.f32 %0, %1, %2;" : "=r"(o.x) : "f"(v0.y), "f"(v0.x));
        asm("cvt.rn.f16x2.f32 %0, %1, %2;" : "=r"(o.y) : "f"(v0.w), "f"(v0.z));
        asm("cvt.rn.f16x2.f32 %0, %1, %2;" : "=r"(o.z) : "f"(v1.y), "f"(v1.x));
        asm("cvt.rn.f16x2.f32 %0, %1, %2;" : "=r"(o.w) : "f"(v1.w), "f"(v1.z));
        dst[i] = o;
    }
}

__device__ __forceinline__ void cp16(uint32_t dst, const __half* src) {
    asm volatile("cp.async.cg.shared.global [%0], [%1], 16;"
                 :: "r"(dst), "l"(src) : "memory");
}
__device__ __forceinline__ void ldsm4(uint32_t& r0, uint32_t& r1,
                                      uint32_t& r2, uint32_t& r3, uint32_t a) {
    asm volatile("ldmatrix.sync.aligned.m8n8.x4.shared.b16 {%0,%1,%2,%3}, [%4];"
                 : "=r"(r0), "=r"(r1), "=r"(r2), "=r"(r3) : "r"(a));
}
__device__ __forceinline__ void stcs2(float* p, float x, float y) {
    asm volatile("st.global.cs.v2.f32 [%0], {%1,%2};"
                 :: "l"(p), "f"(x), "f"(y) : "memory");
}

// 512 threads: per thread 2 A-lines + 4 B-lines of 16B per chunk.
__device__ __forceinline__ void issue_chunk(uint32_t sbase, const __half* Ab,
                                            const __half* Bb, int chunk,
                                            int lr, int lc) {
    uint32_t st = sbase + (chunk & (NSTG - 1)) * STG;
    const int k0 = chunk * BKH + lc * 8;
    #pragma unroll
    for (int i = 0; i < 2; i++) {
        int row = lr + 64 * i;
        cp16(st + row * 128 + ((lc ^ (row & 7)) * 16),
             Ab + (size_t)row * EDIM + k0);
    }
    #pragma unroll
    for (int i = 0; i < 4; i++) {
        int row = lr + 64 * i;
        cp16(st + A_BYTES + row * 128 + ((lc ^ (row & 7)) * 16),
             Bb + (size_t)row * EDIM + k0);
    }
    asm volatile("cp.async.commit_group;" ::: "memory");
}

__global__ __launch_bounds__(512, 1)
void bmm_f16_v10(float* __restrict__ C) {
    extern __shared__ char smem[];
    uint32_t sbase;
    asm("{ .reg .u64 t; cvta.to.shared.u64 t, %1; cvt.u32.u64 %0, t; }"
        : "=r"(sbase) : "l"(smem));

    const int tid  = threadIdx.x;
    const int warp = tid >> 5;
    const int lane = tid & 31;
    const int wm   = warp & 3;        // 4 row blocks of 32
    const int wn   = warp >> 2;       // 4 col blocks of 64
    const int g    = lane >> 2;
    const int t    = lane & 3;

    const int b = blockIdx.z, by = blockIdx.y, bx = blockIdx.x;
    const __half* Ab = (const __half*)g_Ah + ((size_t)b * NDIM + (size_t)by * TM) * EDIM;
    const __half* Bb = (const __half*)g_Bh + ((size_t)b * MDIM + (size_t)bx * TN) * EDIM;

    const int lr = tid >> 3;          // 0..63
    const int lc = tid & 7;

    const int aRowB = wm * 32 + (lane & 15);                  // + i*16
    const int aHi   = lane >> 4;
    const int bRowB = wn * 64 + (lane & 7) + ((lane >> 4) & 1) * 8;  // + j2*16
    const int bHi   = (lane >> 3) & 1;

    float acc[2][8][4];
    #pragma unroll
    for (int i = 0; i < 2; i++)
        #pragma unroll
        for (int j = 0; j < 8; j++)
            #pragma unroll
            for (int r = 0; r < 4; r++) acc[i][j][r] = 0.f;

    issue_chunk(sbase, Ab, Bb, 0, lr, lc);
    issue_chunk(sbase, Ab, Bb, 1, lr, lc);
    issue_chunk(sbase, Ab, Bb, 2, lr, lc);

    for (int c = 0; c < NCHUNK; c++) {
        asm volatile("cp.async.wait_group 2;" ::: "memory");
        __syncthreads();
        if (c + 3 < NCHUNK)
            issue_chunk(sbase, Ab, Bb, c + 3, lr, lc);
        else
            asm volatile("cp.async.commit_group;" ::: "memory");

        uint32_t sa = sbase + (c & (NSTG - 1)) * STG;
        uint32_t sb = sa + A_BYTES;

        #pragma unroll
        for (int s0 = 0; s0 < 4; s0++) {
            const int s = (s0 + wn) & 3;   // per-warp k-step rotation
            // --- hoisted fragment loads: 6 LDSM back-to-back (MLP) ---
            uint32_t af[2][4], bf[4][4];
            #pragma unroll
            for (int i = 0; i < 2; i++) {
                int row = aRowB + i * 16;
                ldsm4(af[i][0], af[i][1], af[i][2], af[i][3],
                      sa + row * 128 + (((2 * s + aHi) ^ (row & 7)) * 16));
            }
            #pragma unroll
            for (int j2 = 0; j2 < 4; j2++) {
                int row = bRowB + j2 * 16;
                ldsm4(bf[j2][0], bf[j2][1], bf[j2][2], bf[j2][3],
                      sb + row * 128 + (((2 * s + bHi) ^ (row & 7)) * 16));
            }
            // --- 64 MMAs ---
            #pragma unroll
            for (int i = 0; i < 2; i++) {
                #pragma unroll
                for (int j2 = 0; j2 < 4; j2++) {
                    asm volatile(
                        "mma.sync.aligned.m16n8k16.row.col.f32.f16.f16.f32 "
                        "{%0,%1,%2,%3}, {%4,%5,%6,%7}, {%8,%9}, {%0,%1,%2,%3};\n"
                        : "+f"(acc[i][2*j2][0]), "+f"(acc[i][2*j2][1]),
                          "+f"(acc[i][2*j2][2]), "+f"(acc[i][2*j2][3])
                        : "r"(af[i][0]), "r"(af[i][1]),
                          "r"(af[i][2]), "r"(af[i][3]),
                          "r"(bf[j2][0]), "r"(bf[j2][1]));
                    asm volatile(
                        "mma.sync.aligned.m16n8k16.row.col.f32.f16.f16.f32 "
                        "{%0,%1,%2,%3}, {%4,%5,%6,%7}, {%8,%9}, {%0,%1,%2,%3};\n"
                        : "+f"(acc[i][2*j2+1][0]), "+f"(acc[i][2*j2+1][1]),
                          "+f"(acc[i][2*j2+1][2]), "+f"(acc[i][2*j2+1][3])
                        : "r"(af[i][0]), "r"(af[i][1]),
                          "r"(af[i][2]), "r"(af[i][3]),
                          "r"(bf[j2][2]), "r"(bf[j2][3]));
                }
            }
        }
    }

    // Epilogue: streaming fp32 stores (keep A/B fp16 tiles resident in L2).
    float* Cb = C + (size_t)b * NDIM * MDIM;
    #pragma unroll
    for (int i = 0; i < 2; i++) {
        int row = by * TM + wm * 32 + i * 16 + g;
        #pragma unroll
        for (int j = 0; j < 8; j++) {
            int col = bx * TN + wn * 64 + j * 8 + 2 * t;
            stcs2(Cb + (size_t)row * MDIM + col, acc[i][j][0], acc[i][j][1]);
            stcs2(Cb + (size_t)(row + 8) * MDIM + col, acc[i][j][2], acc[i][j][3]);
        }
    }
}

extern "C" void kernel_launch(void* const* d_in, const int* in_sizes, int n_in,
                              void* d_out, int out_size) {
    const float* mat0 = (const float*)d_in[0];
    const float* mat1 = (const float*)d_in[1];
    float* out = (float*)d_out;

    uint4* gA; uint4* gB;
    cudaGetSymbolAddress((void**)&gA, g_Ah);
    cudaGetSymbolAddress((void**)&gB, g_Bh);

    const int n8 = NELEM / 8;
    dim3 cgrid(2048, 2, 1);
    cvt_f32_f16<<<cgrid, 256>>>((const float4*)mat0, gA,
                                (const float4*)mat1, gB, n8);

    cudaFuncSetAttribute(bmm_f16_v10,
                         cudaFuncAttributeMaxDynamicSharedMemorySize, SMEM_BYTES);
    dim3 grid(MDIM / TN, NDIM / TM, NB);
    bmm_f16_v10<<<grid, 512, SMEM_BYTES>>>(out);
}

// round 12
// speedup vs baseline: 1.0859x; 1.0859x over previous
#include <cuda_runtime.h>
#include <cuda_fp16.h>
#include <cstdint>

// Batched C[b,n,m] = sum_e A[b,n,e] * B[b,m,e]
// b=8, n=m=2048, e=1024, fp32 in/out.
// v11: cvt pre-kernel fp32->fp16 scratch; GEMM pure fp16 (cp.async 3-stage
// ring, ldmatrix.x4, mma.sync m16n8k16). 128x128 CTA tile, 256 threads,
// 2 CTAs/SM (barrier windows of one CTA covered by the other), 64x32 warp
// tiles, BKH=64, XOR-swizzled 128B rows.

#define TM 128
#define TN 128
#define BKH 64
#define NSTG 3
#define EDIM 1024
#define NDIM 2048
#define MDIM 2048
#define NB 8
#define NCHUNK (EDIM / BKH)      // 16
#define A_BYTES (TM * BKH * 2)   // 16384
#define B_BYTES (TN * BKH * 2)   // 16384
#define STG (A_BYTES + B_BYTES)  // 32768
#define SMEM_BYTES (NSTG * STG)  // 98304  (x2 CTAs = 192KB < 228KB)

#define NELEM (NB * NDIM * EDIM)
__device__ uint4 g_Ah[NELEM / 8];
__device__ uint4 g_Bh[NELEM / 8];

__global__ void __launch_bounds__(256)
cvt_f32_f16(const float4* __restrict__ s0, uint4* __restrict__ d0,
            const float4* __restrict__ s1, uint4* __restrict__ d1, int n8) {
    const float4* src = blockIdx.y ? s1 : s0;
    uint4* dst = blockIdx.y ? d1 : d0;
    int i = blockIdx.x * blockDim.x + threadIdx.x;
    int stride = gridDim.x * blockDim.x;
    for (; i < n8; i += stride) {
        float4 v0 = src[2 * i];
        float4 v1 = src[2 * i + 1];
        uint4 o;
        asm("cvt.rn.f16x2.f32 %0, %1, %2;" : "=r"(o.x) : "f"(v0.y), "f"(v0.x));
        asm("cvt.rn.f16x2.f32 %0, %1, %2;" : "=r"(o.y) : "f"(v0.w), "f"(v0.z));
        asm("cvt.rn.f16x2.f32 %0, %1, %2;" : "=r"(o.z) : "f"(v1.y), "f"(v1.x));
        asm("cvt.rn.f16x2.f32 %0, %1, %2;" : "=r"(o.w) : "f"(v1.w), "f"(v1.z));
        dst[i] = o;
    }
}

__device__ __forceinline__ void cp16(uint32_t dst, const __half* src) {
    asm volatile("cp.async.cg.shared.global [%0], [%1], 16;"
                 :: "r"(dst), "l"(src) : "memory");
}
__device__ __forceinline__ void ldsm4(uint32_t& r0, uint32_t& r1,
                                      uint32_t& r2, uint32_t& r3, uint32_t a) {
    asm volatile("ldmatrix.sync.aligned.m8n8.x4.shared.b16 {%0,%1,%2,%3}, [%4];"
                 : "=r"(r0), "=r"(r1), "=r"(r2), "=r"(r3) : "r"(a));
}

// 256 threads: per thread 4 A-lines + 4 B-lines of 16B per chunk.
__device__ __forceinline__ void issue_chunk(uint32_t sbase, const __half* Ab,
                                            const __half* Bb, int chunk,
                                            int lr, int lc) {
    uint32_t st = sbase + ((chunk % NSTG)) * STG;
    const int k0 = chunk * BKH + lc * 8;
    #pragma unroll
    for (int i = 0; i < 4; i++) {
        int row = lr + 32 * i;
        cp16(st + row * 128 + ((lc ^ (row & 7)) * 16),
             Ab + (size_t)row * EDIM + k0);
    }
    #pragma unroll
    for (int i = 0; i < 4; i++) {
        int row = lr + 32 * i;
        cp16(st + A_BYTES + row * 128 + ((lc ^ (row & 7)) * 16),
             Bb + (size_t)row * EDIM + k0);
    }
    asm volatile("cp.async.commit_group;" ::: "memory");
}

__global__ __launch_bounds__(256, 2)
void bmm_f16_v11(float* __restrict__ C) {
    extern __shared__ char smem[];
    uint32_t sbase;
    asm("{ .reg .u64 t; cvta.to.shared.u64 t, %1; cvt.u32.u64 %0, t; }"
        : "=r"(sbase) : "l"(smem));

    const int tid  = threadIdx.x;
    const int warp = tid >> 5;
    const int lane = tid & 31;
    const int wm   = warp & 1;        // 2 row blocks of 64
    const int wn   = warp >> 1;       // 4 col blocks of 32
    const int g    = lane >> 2;
    const int t    = lane & 3;

    const int b = blockIdx.z, by = blockIdx.y, bx = blockIdx.x;
    const __half* Ab = (const __half*)g_Ah + ((size_t)b * NDIM + (size_t)by * TM) * EDIM;
    const __half* Bb = (const __half*)g_Bh + ((size_t)b * MDIM + (size_t)bx * TN) * EDIM;

    const int lr = tid >> 3;          // 0..31
    const int lc = tid & 7;

    const int aRowB = wm * 64 + (lane & 15);                  // + i*16
    const int aHi   = lane >> 4;
    const int bRowB = wn * 32 + (lane & 7) + ((lane >> 4) & 1) * 8;  // + j2*16
    const int bHi   = (lane >> 3) & 1;

    float acc[4][4][4];
    #pragma unroll
    for (int i = 0; i < 4; i++)
        #pragma unroll
        for (int j = 0; j < 4; j++)
            #pragma unroll
            for (int r = 0; r < 4; r++) acc[i][j][r] = 0.f;

    issue_chunk(sbase, Ab, Bb, 0, lr, lc);
    issue_chunk(sbase, Ab, Bb, 1, lr, lc);

    for (int c = 0; c < NCHUNK; c++) {
        asm volatile("cp.async.wait_group 1;" ::: "memory");
        __syncthreads();
        if (c + 2 < NCHUNK)
            issue_chunk(sbase, Ab, Bb, c + 2, lr, lc);
        else
            asm volatile("cp.async.commit_group;" ::: "memory");

        uint32_t sa = sbase + (c % NSTG) * STG;
        uint32_t sb = sa + A_BYTES;

        #pragma unroll
        for (int s = 0; s < 4; s++) {
            // hoisted fragment loads: 6 LDSM back-to-back
            uint32_t af[4][4], bf[2][4];
            #pragma unroll
            for (int i = 0; i < 4; i++) {
                int row = aRowB + i * 16;
                ldsm4(af[i][0], af[i][1], af[i][2], af[i][3],
                      sa + row * 128 + (((2 * s + aHi) ^ (row & 7)) * 16));
            }
            #pragma unroll
            for (int j2 = 0; j2 < 2; j2++) {
                int row = bRowB + j2 * 16;
                ldsm4(bf[j2][0], bf[j2][1], bf[j2][2], bf[j2][3],
                      sb + row * 128 + (((2 * s + bHi) ^ (row & 7)) * 16));
            }
            // 16 MMAs
            #pragma unroll
            for (int i = 0; i < 4; i++) {
                #pragma unroll
                for (int j2 = 0; j2 < 2; j2++) {
                    asm volatile(
                        "mma.sync.aligned.m16n8k16.row.col.f32.f16.f16.f32 "
                        "{%0,%1,%2,%3}, {%4,%5,%6,%7}, {%8,%9}, {%0,%1,%2,%3};\n"
                        : "+f"(acc[i][2*j2][0]), "+f"(acc[i][2*j2][1]),
                          "+f"(acc[i][2*j2][2]), "+f"(acc[i][2*j2][3])
                        : "r"(af[i][0]), "r"(af[i][1]),
                          "r"(af[i][2]), "r"(af[i][3]),
                          "r"(bf[j2][0]), "r"(bf[j2][1]));
                    asm volatile(
                        "mma.sync.aligned.m16n8k16.row.col.f32.f16.f16.f32 "
                        "{%0,%1,%2,%3}, {%4,%5,%6,%7}, {%8,%9}, {%0,%1,%2,%3};\n"
                        : "+f"(acc[i][2*j2+1][0]), "+f"(acc[i][2*j2+1][1]),
                          "+f"(acc[i][2*j2+1][2]), "+f"(acc[i][2*j2+1][3])
                        : "r"(af[i][0]), "r"(af[i][1]),
                          "r"(af[i][2]), "r"(af[i][3]),
                          "r"(bf[j2][2]), "r"(bf[j2][3]));
                }
            }
        }
    }

    float* Cb = C + (size_t)b * NDIM * MDIM;
    #pragma unroll
    for (int i = 0; i < 4; i++) {
        int row = by * TM + wm * 64 + i * 16 + g;
        #pragma unroll
        for (int j = 0; j < 4; j++) {
            int col = bx * TN + wn * 32 + j * 8 + 2 * t;
            *(float2*)(Cb + (size_t)row * MDIM + col) =
                make_float2(acc[i][j][0], acc[i][j][1]);
            *(float2*)(Cb + (size_t)(row + 8) * MDIM + col) =
                make_float2(acc[i][j][2], acc[i][j][3]);
        }
    }
}

extern "C" void kernel_launch(void* const* d_in, const int* in_sizes, int n_in,
                              void* d_out, int out_size) {
    const float* mat0 = (const float*)d_in[0];
    const float* mat1 = (const float*)d_in[1];
    float* out = (float*)d_out;

    uint4* gA; uint4* gB;
    cudaGetSymbolAddress((void**)&gA, g_Ah);
    cudaGetSymbolAddress((void**)&gB, g_Bh);

    const int n8 = NELEM / 8;
    dim3 cgrid(2048, 2, 1);
    cvt_f32_f16<<<cgrid, 256>>>((const float4*)mat0, gA,
                                (const float4*)mat1, gB, n8);

    cudaFuncSetAttribute(bmm_f16_v11,
                         cudaFuncAttributeMaxDynamicSharedMemorySize, SMEM_BYTES);
    dim3 grid(MDIM / TN, NDIM / TM, NB);   // (16, 16, 8) = 2048 CTAs
    bmm_f16_v11<<<grid, 256, SMEM_BYTES>>>(out);
}

// round 13
// speedup vs baseline: 1.1010x; 1.0139x over previous
#include <cuda_runtime.h>
#include <cuda_fp16.h>
#include <cstdint>

// Batched C[b,n,m] = sum_e A[b,n,e] * B[b,m,e]
// b=8, n=m=2048, e=1024, fp32 in/out.
// v13: cvt pre-kernel fp32->fp16 scratch; GEMM pure fp16 (cp.async 3-stage
// ring, ldmatrix.x4, mma.sync m16n8k16). 128x128 CTA tile, 128 threads,
// 4 warps (2x2) of 64x64 tiles, 2 CTAs/SM, fragment double-buffering.

#define TM 128
#define TN 128
#define BKH 64
#define NSTG 3
#define EDIM 1024
#define NDIM 2048
#define MDIM 2048
#define NB 8
#define NCHUNK (EDIM / BKH)      // 16
#define A_BYTES (TM * BKH * 2)   // 16384
#define B_BYTES (TN * BKH * 2)   // 16384
#define STG (A_BYTES + B_BYTES)  // 32768
#define SMEM_BYTES (NSTG * STG)  // 98304 (x2 CTAs = 192KB)

#define NELEM (NB * NDIM * EDIM)
__device__ uint4 g_Ah[NELEM / 8];
__device__ uint4 g_Bh[NELEM / 8];

__global__ void __launch_bounds__(256)
cvt_f32_f16(const float4* __restrict__ s0, uint4* __restrict__ d0,
            const float4* __restrict__ s1, uint4* __restrict__ d1, int n8) {
    const float4* src = blockIdx.y ? s1 : s0;
    uint4* dst = blockIdx.y ? d1 : d0;
    int i = blockIdx.x * blockDim.x + threadIdx.x;
    int stride = gridDim.x * blockDim.x;
    for (; i < n8; i += stride) {
        float4 v0 = src[2 * i];
        float4 v1 = src[2 * i + 1];
        uint4 o;
        asm("cvt.rn.f16x2.f32 %0, %1, %2;" : "=r"(o.x) : "f"(v0.y), "f"(v0.x));
        asm("cvt.rn.f16x2.f32 %0, %1, %2;" : "=r"(o.y) : "f"(v0.w), "f"(v0.z));
        asm("cvt.rn.f16x2.f32 %0, %1, %2;" : "=r"(o.z) : "f"(v1.y), "f"(v1.x));
        asm("cvt.rn.f16x2.f32 %0, %1, %2;" : "=r"(o.w) : "f"(v1.w), "f"(v1.z));
        dst[i] = o;
    }
}

__device__ __forceinline__ void cp16(uint32_t dst, const __half* src) {
    asm volatile("cp.async.cg.shared.global [%0], [%1], 16;"
                 :: "r"(dst), "l"(src) : "memory");
}
__device__ __forceinline__ void ldsm4(uint32_t& r0, uint32_t& r1,
                                      uint32_t& r2, uint32_t& r3, uint32_t a) {
    asm volatile("ldmatrix.sync.aligned.m8n8.x4.shared.b16 {%0,%1,%2,%3}, [%4];"
                 : "=r"(r0), "=r"(r1), "=r"(r2), "=r"(r3) : "r"(a));
}

// 128 threads: per thread 8 A-lines + 8 B-lines of 16B per chunk.
__device__ __forceinline__ void issue_chunk(uint32_t sbase, const __half* Ab,
                                            const __half* Bb, int chunk,
                                            int lr, int lc) {
    uint32_t st = sbase + (chunk % NSTG) * STG;
    const int k0 = chunk * BKH + lc * 8;
    #pragma unroll
    for (int i = 0; i < 8; i++) {
        int row = lr + 16 * i;
        cp16(st + row * 128 + ((lc ^ (row & 7)) * 16),
             Ab + (size_t)row * EDIM + k0);
    }
    #pragma unroll
    for (int i = 0; i < 8; i++) {
        int row = lr + 16 * i;
        cp16(st + A_BYTES + row * 128 + ((lc ^ (row & 7)) * 16),
             Bb + (size_t)row * EDIM + k0);
    }
    asm volatile("cp.async.commit_group;" ::: "memory");
}

__global__ __launch_bounds__(128, 2)
void bmm_f16_v13(float* __restrict__ C) {
    extern __shared__ char smem[];
    uint32_t sbase;
    asm("{ .reg .u64 t; cvta.to.shared.u64 t, %1; cvt.u32.u64 %0, t; }"
        : "=r"(sbase) : "l"(smem));

    const int tid  = threadIdx.x;
    const int warp = tid >> 5;
    const int lane = tid & 31;
    const int wm   = warp & 1;        // 2 row blocks of 64
    const int wn   = warp >> 1;       // 2 col blocks of 64
    const int g    = lane >> 2;
    const int t    = lane & 3;

    const int b = blockIdx.z, by = blockIdx.y, bx = blockIdx.x;
    const __half* Ab = (const __half*)g_Ah + ((size_t)b * NDIM + (size_t)by * TM) * EDIM;
    const __half* Bb = (const __half*)g_Bh + ((size_t)b * MDIM + (size_t)bx * TN) * EDIM;

    const int lr = tid >> 3;          // 0..15
    const int lc = tid & 7;

    const int aRowB = wm * 64 + (lane & 15);                  // + i*16
    const int aHi   = lane >> 4;
    const int bRowB = wn * 64 + (lane & 7) + ((lane >> 4) & 1) * 8;  // + j2*16
    const int bHi   = (lane >> 3) & 1;

    float acc[4][8][4];
    #pragma unroll
    for (int i = 0; i < 4; i++)
        #pragma unroll
        for (int j = 0; j < 8; j++)
            #pragma unroll
            for (int r = 0; r < 4; r++) acc[i][j][r] = 0.f;

    issue_chunk(sbase, Ab, Bb, 0, lr, lc);
    issue_chunk(sbase, Ab, Bb, 1, lr, lc);

    uint32_t af[2][4][4], bf[2][4][4];

    #define LOAD_FRAGS(buf, sa, sb, s) do {                                   \
        _Pragma("unroll")                                                     \
        for (int i = 0; i < 4; i++) {                                         \
            int row = aRowB + i * 16;                                         \
            ldsm4(af[buf][i][0], af[buf][i][1],                               \
                  af[buf][i][2], af[buf][i][3],                               \
                  (sa) + row * 128 + ((((2*(s)) + aHi) ^ (row & 7)) * 16));   \
        }                                                                     \
        _Pragma("unroll")                                                     \
        for (int j2 = 0; j2 < 4; j2++) {                                      \
            int row = bRowB + j2 * 16;                                        \
            ldsm4(bf[buf][j2][0], bf[buf][j2][1],                             \
                  bf[buf][j2][2], bf[buf][j2][3],                             \
                  (sb) + row * 128 + ((((2*(s)) + bHi) ^ (row & 7)) * 16));   \
        }                                                                     \
    } while (0)

    for (int c = 0; c < NCHUNK; c++) {
        asm volatile("cp.async.wait_group 1;" ::: "memory");
        __syncthreads();
        if (c + 2 < NCHUNK)
            issue_chunk(sbase, Ab, Bb, c + 2, lr, lc);
        else
            asm volatile("cp.async.commit_group;" ::: "memory");

        uint32_t sa = sbase + (c % NSTG) * STG;
        uint32_t sb = sa + A_BYTES;

        LOAD_FRAGS(0, sa, sb, 0);
        #pragma unroll
        for (int s = 0; s < 4; s++) {
            const int cur = s & 1;
            if (s < 3) LOAD_FRAGS(1 - cur, sa, sb, s + 1);
            #pragma unroll
            for (int i = 0; i < 4; i++) {
                #pragma unroll
                for (int j2 = 0; j2 < 4; j2++) {
                    asm volatile(
                        "mma.sync.aligned.m16n8k16.row.col.f32.f16.f16.f32 "
                        "{%0,%1,%2,%3}, {%4,%5,%6,%7}, {%8,%9}, {%0,%1,%2,%3};\n"
                        : "+f"(acc[i][2*j2][0]), "+f"(acc[i][2*j2][1]),
                          "+f"(acc[i][2*j2][2]), "+f"(acc[i][2*j2][3])
                        : "r"(af[cur][i][0]), "r"(af[cur][i][1]),
                          "r"(af[cur][i][2]), "r"(af[cur][i][3]),
                          "r"(bf[cur][j2][0]), "r"(bf[cur][j2][1]));
                    asm volatile(
                        "mma.sync.aligned.m16n8k16.row.col.f32.f16.f16.f32 "
                        "{%0,%1,%2,%3}, {%4,%5,%6,%7}, {%8,%9}, {%0,%1,%2,%3};\n"
                        : "+f"(acc[i][2*j2+1][0]), "+f"(acc[i][2*j2+1][1]),
                          "+f"(acc[i][2*j2+1][2]), "+f"(acc[i][2*j2+1][3])
                        : "r"(af[cur][i][0]), "r"(af[cur][i][1]),
                          "r"(af[cur][i][2]), "r"(af[cur][i][3]),
                          "r"(bf[cur][j2][2]), "r"(bf[cur][j2][3]));
                }
            }
        }
    }

    float* Cb = C + (size_t)b * NDIM * MDIM;
    #pragma unroll
    for (int i = 0; i < 4; i++) {
        int row = by * TM + wm * 64 + i * 16 + g;
        #pragma unroll
        for (int j = 0; j < 8; j++) {
            int col = bx * TN + wn * 64 + j * 8 + 2 * t;
            *(float2*)(Cb + (size_t)row * MDIM + col) =
                make_float2(acc[i][j][0], acc[i][j][1]);
            *(float2*)(Cb + (size_t)(row + 8) * MDIM + col) =
                make_float2(acc[i][j][2], acc[i][j][3]);
        }
    }
}

extern "C" void kernel_launch(void* const* d_in, const int* in_sizes, int n_in,
                              void* d_out, int out_size) {
    const float* mat0 = (const float*)d_in[0];
    const float* mat1 = (const float*)d_in[1];
    float* out = (float*)d_out;

    uint4* gA; uint4* gB;
    cudaGetSymbolAddress((void**)&gA, g_Ah);
    cudaGetSymbolAddress((void**)&gB, g_Bh);

    const int n8 = NELEM / 8;
    dim3 cgrid(2048, 2, 1);
    cvt_f32_f16<<<cgrid, 256>>>((const float4*)mat0, gA,
                                (const float4*)mat1, gB, n8);

    cudaFuncSetAttribute(bmm_f16_v13,
                         cudaFuncAttributeMaxDynamicSharedMemorySize, SMEM_BYTES);
    dim3 grid(MDIM / TN, NDIM / TM, NB);   // (16, 16, 8) = 2048 CTAs
    bmm_f16_v13<<<grid, 128, SMEM_BYTES>>>(out);
}

// round 15
// speedup vs baseline: 1.1643x; 1.0574x over previous
#include <cuda_runtime.h>
#include <cuda_fp16.h>
#include <cstdint>

// Batched C[b,n,m] = sum_e A[b,n,e] * B[b,m,e]
// b=8, n=m=2048, e=1024, fp32 in/out.
// v14: v13 (cvt pre-kernel fp32->fp16; GEMM: cp.async 3-stage ring,
// ldmatrix.x4, mma.sync m16n8k16; 128x128 CTA, 128 thr, 2x2 warps of 64x64,
// 2 CTAs/SM, frag double-buffer) + cp.async spread over k-steps (quarter
// bursts) to decorrelate the two CTAs' LSU queue pressure.

#define TM 128
#define TN 128
#define BKH 64
#define NSTG 3
#define EDIM 1024
#define NDIM 2048
#define MDIM 2048
#define NB 8
#define NCHUNK (EDIM / BKH)      // 16
#define A_BYTES (TM * BKH * 2)   // 16384
#define B_BYTES (TN * BKH * 2)   // 16384
#define STG (A_BYTES + B_BYTES)  // 32768
#define SMEM_BYTES (NSTG * STG)  // 98304 (x2 CTAs = 192KB)

#define NELEM (NB * NDIM * EDIM)
__device__ uint4 g_Ah[NELEM / 8];
__device__ uint4 g_Bh[NELEM / 8];

__global__ void __launch_bounds__(256)
cvt_f32_f16(const float4* __restrict__ s0, uint4* __restrict__ d0,
            const float4* __restrict__ s1, uint4* __restrict__ d1, int n8) {
    const float4* src = blockIdx.y ? s1 : s0;
    uint4* dst = blockIdx.y ? d1 : d0;
    int i = blockIdx.x * blockDim.x + threadIdx.x;
    int stride = gridDim.x * blockDim.x;
    for (; i < n8; i += stride) {
        float4 v0 = src[2 * i];
        float4 v1 = src[2 * i + 1];
        uint4 o;
        asm("cvt.rn.f16x2.f32 %0, %1, %2;" : "=r"(o.x) : "f"(v0.y), "f"(v0.x));
        asm("cvt.rn.f16x2.f32 %0, %1, %2;" : "=r"(o.y) : "f"(v0.w), "f"(v0.z));
        asm("cvt.rn.f16x2.f32 %0, %1, %2;" : "=r"(o.z) : "f"(v1.y), "f"(v1.x));
        asm("cvt.rn.f16x2.f32 %0, %1, %2;" : "=r"(o.w) : "f"(v1.w), "f"(v1.z));
        dst[i] = o;
    }
}

__device__ __forceinline__ void cp16(uint32_t dst, const __half* src) {
    asm volatile("cp.async.cg.shared.global [%0], [%1], 16;"
                 :: "r"(dst), "l"(src) : "memory");
}
__device__ __forceinline__ void ldsm4(uint32_t& r0, uint32_t& r1,
                                      uint32_t& r2, uint32_t& r3, uint32_t a) {
    asm volatile("ldmatrix.sync.aligned.m8n8.x4.shared.b16 {%0,%1,%2,%3}, [%4];"
                 : "=r"(r0), "=r"(r1), "=r"(r2), "=r"(r3) : "r"(a));
}

// Full-chunk issue (prologue only): 8 A-lines + 8 B-lines of 16B per thread.
__device__ __forceinline__ void issue_chunk(uint32_t sbase, const __half* Ab,
                                            const __half* Bb, int chunk,
                                            int lr, int lc) {
    uint32_t st = sbase + (chunk % NSTG) * STG;
    const int k0 = chunk * BKH + lc * 8;
    #pragma unroll
    for (int i = 0; i < 8; i++) {
        int row = lr + 16 * i;
        cp16(st + row * 128 + ((lc ^ (row & 7)) * 16),
             Ab + (size_t)row * EDIM + k0);
    }
    #pragma unroll
    for (int i = 0; i < 8; i++) {
        int row = lr + 16 * i;
        cp16(st + A_BYTES + row * 128 + ((lc ^ (row & 7)) * 16),
             Bb + (size_t)row * EDIM + k0);
    }
    asm volatile("cp.async.commit_group;" ::: "memory");
}

// Quarter issue (mainloop): 2 A-lines + 2 B-lines; no commit (one per iter).
__device__ __forceinline__ void issue_quarter(uint32_t sbase, const __half* Ab,
                                              const __half* Bb, int chunk,
                                              int q, int lr, int lc) {
    uint32_t st = sbase + (chunk % NSTG) * STG;
    const int k0 = chunk * BKH + lc * 8;
    #pragma unroll
    for (int i = 2 * q; i < 2 * q + 2; i++) {
        int row = lr + 16 * i;
        cp16(st + row * 128 + ((lc ^ (row & 7)) * 16),
             Ab + (size_t)row * EDIM + k0);
    }
    #pragma unroll
    for (int i = 2 * q; i < 2 * q + 2; i++) {
        int row = lr + 16 * i;
        cp16(st + A_BYTES + row * 128 + ((lc ^ (row & 7)) * 16),
             Bb + (size_t)row * EDIM + k0);
    }
}

__global__ __launch_bounds__(128, 2)
void bmm_f16_v14(float* __restrict__ C) {
    extern __shared__ char smem[];
    uint32_t sbase;
    asm("{ .reg .u64 t; cvta.to.shared.u64 t, %1; cvt.u32.u64 %0, t; }"
        : "=r"(sbase) : "l"(smem));

    const int tid  = threadIdx.x;
    const int warp = tid >> 5;
    const int lane = tid & 31;
    const int wm   = warp & 1;        // 2 row blocks of 64
    const int wn   = warp >> 1;       // 2 col blocks of 64
    const int g    = lane >> 2;
    const int t    = lane & 3;

    const int b = blockIdx.z, by = blockIdx.y, bx = blockIdx.x;
    const __half* Ab = (const __half*)g_Ah + ((size_t)b * NDIM + (size_t)by * TM) * EDIM;
    const __half* Bb = (const __half*)g_Bh + ((size_t)b * MDIM + (size_t)bx * TN) * EDIM;

    const int lr = tid >> 3;          // 0..15
    const int lc = tid & 7;

    const int aRowB = wm * 64 + (lane & 15);                  // + i*16
    const int aHi   = lane >> 4;
    const int bRowB = wn * 64 + (lane & 7) + ((lane >> 4) & 1) * 8;  // + j2*16
    const int bHi   = (lane >> 3) & 1;

    float acc[4][8][4];
    #pragma unroll
    for (int i = 0; i < 4; i++)
        #pragma unroll
        for (int j = 0; j < 8; j++)
            #pragma unroll
            for (int r = 0; r < 4; r++) acc[i][j][r] = 0.f;

    issue_chunk(sbase, Ab, Bb, 0, lr, lc);
    issue_chunk(sbase, Ab, Bb, 1, lr, lc);

    uint32_t af[2][4][4], bf[2][4][4];

    #define LOAD_FRAGS(buf, sa, sb, s) do {                                   \
        _Pragma("unroll")                                                     \
        for (int i = 0; i < 4; i++) {                                         \
            int row = aRowB + i * 16;                                         \
            ldsm4(af[buf][i][0], af[buf][i][1],                               \
                  af[buf][i][2], af[buf][i][3],                               \
                  (sa) + row * 128 + ((((2*(s)) + aHi) ^ (row & 7)) * 16));   \
        }                                                                     \
        _Pragma("unroll")                                                     \
        for (int j2 = 0; j2 < 4; j2++) {                                      \
            int row = bRowB + j2 * 16;                                        \
            ldsm4(bf[buf][j2][0], bf[buf][j2][1],                             \
                  bf[buf][j2][2], bf[buf][j2][3],                             \
                  (sb) + row * 128 + ((((2*(s)) + bHi) ^ (row & 7)) * 16));   \
        }                                                                     \
    } while (0)

    for (int c = 0; c < NCHUNK; c++) {
        asm volatile("cp.async.wait_group 1;" ::: "memory");
        __syncthreads();

        const bool pf = (c + 2 < NCHUNK);
        uint32_t sa = sbase + (c % NSTG) * STG;
        uint32_t sb = sa + A_BYTES;

        LOAD_FRAGS(0, sa, sb, 0);
        #pragma unroll
        for (int s = 0; s < 4; s++) {
            const int cur = s & 1;
            if (s < 3) LOAD_FRAGS(1 - cur, sa, sb, s + 1);
            if (pf) issue_quarter(sbase, Ab, Bb, c + 2, s, lr, lc);
            #pragma unroll
            for (int i = 0; i < 4; i++) {
                #pragma unroll
                for (int j2 = 0; j2 < 4; j2++) {
                    asm volatile(
                        "mma.sync.aligned.m16n8k16.row.col.f32.f16.f16.f32 "
                        "{%0,%1,%2,%3}, {%4,%5,%6,%7}, {%8,%9}, {%0,%1,%2,%3};\n"
                        : "+f"(acc[i][2*j2][0]), "+f"(acc[i][2*j2][1]),
                          "+f"(acc[i][2*j2][2]), "+f"(acc[i][2*j2][3])
                        : "r"(af[cur][i][0]), "r"(af[cur][i][1]),
                          "r"(af[cur][i][2]), "r"(af[cur][i][3]),
                          "r"(bf[cur][j2][0]), "r"(bf[cur][j2][1]));
                    asm volatile(
                        "mma.sync.aligned.m16n8k16.row.col.f32.f16.f16.f32 "
                        "{%0,%1,%2,%3}, {%4,%5,%6,%7}, {%8,%9}, {%0,%1,%2,%3};\n"
                        : "+f"(acc[i][2*j2+1][0]), "+f"(acc[i][2*j2+1][1]),
                          "+f"(acc[i][2*j2+1][2]), "+f"(acc[i][2*j2+1][3])
                        : "r"(af[cur][i][0]), "r"(af[cur][i][1]),
                          "r"(af[cur][i][2]), "r"(af[cur][i][3]),
                          "r"(bf[cur][j2][2]), "r"(bf[cur][j2][3]));
                }
            }
        }
        // one group per iteration (empty in tail) keeps wait_group accounting
        asm volatile("cp.async.commit_group;" ::: "memory");
    }

    float* Cb = C + (size_t)b * NDIM * MDIM;
    #pragma unroll
    for (int i = 0; i < 4; i++) {
        int row = by * TM + wm * 64 + i * 16 + g;
        #pragma unroll
        for (int j = 0; j < 8; j++) {
            int col = bx * TN + wn * 64 + j * 8 + 2 * t;
            *(float2*)(Cb + (size_t)row * MDIM + col) =
                make_float2(acc[i][j][0], acc[i][j][1]);
            *(float2*)(Cb + (size_t)(row + 8) * MDIM + col) =
                make_float2(acc[i][j][2], acc[i][j][3]);
        }
    }
}

extern "C" void kernel_launch(void* const* d_in, const int* in_sizes, int n_in,
                              void* d_out, int out_size) {
    const float* mat0 = (const float*)d_in[0];
    const float* mat1 = (const float*)d_in[1];
    float* out = (float*)d_out;

    uint4* gA; uint4* gB;
    cudaGetSymbolAddress((void**)&gA, g_Ah);
    cudaGetSymbolAddress((void**)&gB, g_Bh);

    const int n8 = NELEM / 8;
    dim3 cgrid(2048, 2, 1);
    cvt_f32_f16<<<cgrid, 256>>>((const float4*)mat0, gA,
                                (const float4*)mat1, gB, n8);

    cudaFuncSetAttribute(bmm_f16_v14,
                         cudaFuncAttributeMaxDynamicSharedMemorySize, SMEM_BYTES);
    dim3 grid(MDIM / TN, NDIM / TM, NB);   // (16, 16, 8) = 2048 CTAs
    bmm_f16_v14<<<grid, 128, SMEM_BYTES>>>(out);
}